// round 6
// baseline (speedup 1.0000x reference)
#include <cuda_runtime.h>
#include <stdint.h>

#define NUM_NODES 50000
#define NUM_EDGES 600000
#define DD 128
#define FF 128

#define BK 16
#define A_STR 20    // 16 k + 4 pad -> conflict-free frag loads
#define B_STR 136   // 128 n + 8 pad -> conflict-free frag loads

// smem layout (uint32 units) inside one dynamic block
#define AH_OFF 0
#define AL_OFF (AH_OFF + 2 * 128 * A_STR)
#define BH_OFF (AL_OFF + 2 * 128 * A_STR)
#define BL_OFF (BH_OFF + 2 * BK * B_STR)
#define SMEM_WORDS (BL_OFF + 2 * BK * B_STR)
#define SMEM_BYTES (SMEM_WORDS * 4)   // 75776

// Scratch
__device__ float g_agg[NUM_NODES * DD];
__device__ int g_is64;
__device__ int g_start[NUM_NODES];   // CSR row starts
__device__ int g_cur[NUM_NODES];     // counts -> cursors -> row ends
__device__ int g_src[NUM_EDGES];     // source id per CSR slot
__device__ uint32_t g_Wh[256 * FF], g_Wl[256 * FF];  // pre-split W

// ---------------------------------------------------------------------------
// Detect index dtype (int64 vs int32) from data pattern. Deterministic.
// ---------------------------------------------------------------------------
__global__ void detect_kernel(const int* __restrict__ w) {
    __shared__ int cnt;
    if (threadIdx.x == 0) cnt = 0;
    __syncthreads();
    int nz = 0;
    for (int i = threadIdx.x * 2 + 1; i < 2048; i += 2 * blockDim.x)
        nz += (w[i] != 0);
    atomicAdd(&cnt, nz);
    __syncthreads();
    if (threadIdx.x == 0) g_is64 = (cnt < 512) ? 1 : 0;
}

// ---------------------------------------------------------------------------
// Pre-split W into tf32 hi/lo (runs once per launch; W is tiny)
// ---------------------------------------------------------------------------
__device__ __forceinline__ void cvt_split(float f, uint32_t& h, uint32_t& l) {
    asm("cvt.rna.tf32.f32 %0, %1;" : "=r"(h) : "f"(f));
    float r = f - __uint_as_float(h);
    asm("cvt.rna.tf32.f32 %0, %1;" : "=r"(l) : "f"(r));
}

__global__ void split_w_kernel(const float* __restrict__ W) {
    int i = blockIdx.x * blockDim.x + threadIdx.x;
    if (i < 256 * FF) {
        uint32_t h, l;
        cvt_split(W[i], h, l);
        g_Wh[i] = h; g_Wl[i] = l;
    }
}

// ---------------------------------------------------------------------------
// CSR build
// ---------------------------------------------------------------------------
__global__ void clear_count_kernel() {
    int i = blockIdx.x * blockDim.x + threadIdx.x;
    if (i < NUM_NODES) g_cur[i] = 0;
}

__global__ void count_kernel(const void* __restrict__ tgt) {
    int e = blockIdx.x * blockDim.x + threadIdx.x;
    if (e >= NUM_EDGES) return;
    int t = g_is64 ? (int)reinterpret_cast<const long long*>(tgt)[e]
                   : reinterpret_cast<const int*>(tgt)[e];
    atomicAdd(&g_cur[t], 1);
}

// Single-block exclusive scan over 50K counts. Writes prefix into both
// g_start (persistent row start) and g_cur (placement cursor).
__global__ void scan_kernel() {
    __shared__ int sh[1024];
    int t = threadIdx.x;
    const int CHUNK = (NUM_NODES + 1023) / 1024;  // 49
    int lo = t * CHUNK;
    int hi = min(lo + CHUNK, NUM_NODES);

    int sum = 0;
    for (int i = lo; i < hi; i++) sum += g_cur[i];
    sh[t] = sum;
    __syncthreads();
    for (int off = 1; off < 1024; off <<= 1) {
        int v = 0;
        if (t >= off) v = sh[t - off];
        __syncthreads();
        sh[t] += v;
        __syncthreads();
    }
    int run = sh[t] - sum;  // exclusive prefix of this thread's chunk
    for (int i = lo; i < hi; i++) {
        int c = g_cur[i];
        g_start[i] = run;
        g_cur[i] = run;
        run += c;
    }
}

__global__ void place_kernel(const void* __restrict__ src,
                             const void* __restrict__ tgt) {
    int e = blockIdx.x * blockDim.x + threadIdx.x;
    if (e >= NUM_EDGES) return;
    int s, t;
    if (g_is64) {
        s = (int)reinterpret_cast<const long long*>(src)[e];
        t = (int)reinterpret_cast<const long long*>(tgt)[e];
    } else {
        s = reinterpret_cast<const int*>(src)[e];
        t = reinterpret_cast<const int*>(tgt)[e];
    }
    int pos = atomicAdd(&g_cur[t], 1);
    g_src[pos] = s;
}

// ---------------------------------------------------------------------------
// Gather: one warp per node, register accumulation, single write per row.
// After place_kernel, g_cur[n] == row end.
// ---------------------------------------------------------------------------
__global__ void gather_kernel(const float* __restrict__ x) {
    int n = (blockIdx.x * blockDim.x + threadIdx.x) >> 5;
    if (n >= NUM_NODES) return;
    int lane = threadIdx.x & 31;

    int beg = g_start[n], end = g_cur[n];
    float4 acc = make_float4(0.f, 0.f, 0.f, 0.f);

    int j = beg;
    for (; j + 4 <= end; j += 4) {
        int s0 = g_src[j], s1 = g_src[j + 1], s2 = g_src[j + 2], s3 = g_src[j + 3];
        float4 v0 = reinterpret_cast<const float4*>(x + (long long)s0 * DD)[lane];
        float4 v1 = reinterpret_cast<const float4*>(x + (long long)s1 * DD)[lane];
        float4 v2 = reinterpret_cast<const float4*>(x + (long long)s2 * DD)[lane];
        float4 v3 = reinterpret_cast<const float4*>(x + (long long)s3 * DD)[lane];
        acc.x += v0.x + v1.x + v2.x + v3.x;
        acc.y += v0.y + v1.y + v2.y + v3.y;
        acc.z += v0.z + v1.z + v2.z + v3.z;
        acc.w += v0.w + v1.w + v2.w + v3.w;
    }
    for (; j < end; j++) {
        int s = g_src[j];
        float4 v = reinterpret_cast<const float4*>(x + (long long)s * DD)[lane];
        acc.x += v.x; acc.y += v.y; acc.z += v.z; acc.w += v.w;
    }
    reinterpret_cast<float4*>(g_agg + (long long)n * DD)[lane] = acc;
}

// ---------------------------------------------------------------------------
// Tensor-core GEMM via 3xTF32: out = [agg|x] @ W + b,  M=50000, N=128, K=256.
// ---------------------------------------------------------------------------
__device__ __forceinline__ void mma_tf32(float* d, const uint32_t* a,
                                         uint32_t b0, uint32_t b1) {
    asm volatile(
        "mma.sync.aligned.m16n8k8.row.col.f32.tf32.tf32.f32 "
        "{%0,%1,%2,%3}, {%4,%5,%6,%7}, {%8,%9}, {%0,%1,%2,%3};"
        : "+f"(d[0]), "+f"(d[1]), "+f"(d[2]), "+f"(d[3])
        : "r"(a[0]), "r"(a[1]), "r"(a[2]), "r"(a[3]), "r"(b0), "r"(b1));
}

__device__ __forceinline__ void load_chunk(
    const float* __restrict__ hbase, int k0,
    uint32_t* __restrict__ Ah, uint32_t* __restrict__ Al,
    uint32_t* __restrict__ Bh, uint32_t* __restrict__ Bl,
    int tid, int nbase)
{
    // A: 128 rows x 16 k, split on the fly
    #pragma unroll
    for (int i = 0; i < 2; i++) {
        int idx = tid + i * 256;
        int r = idx >> 2, q = idx & 3;
        int node = nbase + r;
        float4 v = make_float4(0.f, 0.f, 0.f, 0.f);
        if (node < NUM_NODES)
            v = *reinterpret_cast<const float4*>(hbase + (long long)node * DD + q * 4);
        uint32_t h0,l0,h1,l1,h2,l2,h3,l3;
        cvt_split(v.x, h0, l0); cvt_split(v.y, h1, l1);
        cvt_split(v.z, h2, l2); cvt_split(v.w, h3, l3);
        int o = r * A_STR + q * 4;
        Ah[o] = h0; Ah[o+1] = h1; Ah[o+2] = h2; Ah[o+3] = h3;
        Al[o] = l0; Al[o+1] = l1; Al[o+2] = l2; Al[o+3] = l3;
    }
    // B: pre-split W rows k0..k0+15, pure copies
    #pragma unroll
    for (int i = 0; i < 2; i++) {
        int idx = tid + i * 256;
        int r = idx >> 5, q = idx & 31;
        uint4 vh = *reinterpret_cast<const uint4*>(g_Wh + (k0 + r) * FF + q * 4);
        uint4 vl = *reinterpret_cast<const uint4*>(g_Wl + (k0 + r) * FF + q * 4);
        int o = r * B_STR + q * 4;
        *reinterpret_cast<uint4*>(Bh + o) = vh;
        *reinterpret_cast<uint4*>(Bl + o) = vl;
    }
}

__global__ void __launch_bounds__(256, 2)
gemm_kernel(const float* __restrict__ x,
            const float* __restrict__ b, float* __restrict__ out) {
    extern __shared__ uint32_t smem[];
    uint32_t* AhB = smem + AH_OFF;
    uint32_t* AlB = smem + AL_OFF;
    uint32_t* BhB = smem + BH_OFF;
    uint32_t* BlB = smem + BL_OFF;

    int tid = threadIdx.x;
    int lane = tid & 31, wid = tid >> 5;
    int gid = lane >> 2, tig = lane & 3;
    int wm = wid & 3;
    int wn = wid >> 2;
    int nbase = blockIdx.x * 128;

    float acc[2][8][4];
    #pragma unroll
    for (int mt = 0; mt < 2; mt++)
        #pragma unroll
        for (int nt = 0; nt < 8; nt++)
            #pragma unroll
            for (int f = 0; f < 4; f++) acc[mt][nt][f] = 0.f;

    load_chunk(g_agg, 0, AhB, AlB, BhB, BlB, tid, nbase);
    __syncthreads();

    for (int c = 0; c < 16; c++) {
        if (c + 1 < 16) {
            int k0 = (c + 1) * BK;
            const float* hbase = (k0 < 128) ? (g_agg + k0) : (x + k0 - 128);
            int nb = (c + 1) & 1;
            load_chunk(hbase, k0,
                       AhB + nb * 128 * A_STR, AlB + nb * 128 * A_STR,
                       BhB + nb * BK * B_STR,  BlB + nb * BK * B_STR,
                       tid, nbase);
        }
        int cb = c & 1;
        const uint32_t* cAh = AhB + cb * 128 * A_STR;
        const uint32_t* cAl = AlB + cb * 128 * A_STR;
        const uint32_t* cBh = BhB + cb * BK * B_STR;
        const uint32_t* cBl = BlB + cb * BK * B_STR;

        #pragma unroll
        for (int ks = 0; ks < 2; ks++) {
            uint32_t ah[2][4], al[2][4];
            #pragma unroll
            for (int mt = 0; mt < 2; mt++) {
                int m = wm * 32 + mt * 16 + gid;
                int ro = m * A_STR + ks * 8 + tig;
                ah[mt][0] = cAh[ro];
                ah[mt][1] = cAh[ro + 8 * A_STR];
                ah[mt][2] = cAh[ro + 4];
                ah[mt][3] = cAh[ro + 8 * A_STR + 4];
                al[mt][0] = cAl[ro];
                al[mt][1] = cAl[ro + 8 * A_STR];
                al[mt][2] = cAl[ro + 4];
                al[mt][3] = cAl[ro + 8 * A_STR + 4];
            }
            #pragma unroll
            for (int nt = 0; nt < 8; nt++) {
                int n = wn * 64 + nt * 8 + gid;
                int bo = (ks * 8 + tig) * B_STR + n;
                uint32_t b0h = cBh[bo], b1h = cBh[bo + 4 * B_STR];
                uint32_t b0l = cBl[bo], b1l = cBl[bo + 4 * B_STR];
                #pragma unroll
                for (int mt = 0; mt < 2; mt++) {
                    mma_tf32(acc[mt][nt], ah[mt], b0h, b1h);
                    mma_tf32(acc[mt][nt], ah[mt], b0l, b1l);
                    mma_tf32(acc[mt][nt], al[mt], b0h, b1h);
                }
            }
        }
        __syncthreads();
    }

    #pragma unroll
    for (int mt = 0; mt < 2; mt++) {
        #pragma unroll
        for (int nt = 0; nt < 8; nt++) {
            int col = wn * 64 + nt * 8 + tig * 2;
            float2 bb = *reinterpret_cast<const float2*>(b + col);
            int row0 = nbase + wm * 32 + mt * 16 + gid;
            if (row0 < NUM_NODES) {
                float2 o = make_float2(acc[mt][nt][0] + bb.x, acc[mt][nt][1] + bb.y);
                *reinterpret_cast<float2*>(out + (long long)row0 * FF + col) = o;
            }
            int row1 = row0 + 8;
            if (row1 < NUM_NODES) {
                float2 o = make_float2(acc[mt][nt][2] + bb.x, acc[mt][nt][3] + bb.y);
                *reinterpret_cast<float2*>(out + (long long)row1 * FF + col) = o;
            }
        }
    }
}

extern "C" void kernel_launch(void* const* d_in, const int* in_sizes, int n_in,
                              void* d_out, int out_size) {
    const float* node_x = (const float*)d_in[0];
    const void*  sources = d_in[1];
    const void*  targets = d_in[2];
    const float* W = (const float*)d_in[3];
    const float* b = (const float*)d_in[4];
    float* out = (float*)d_out;

    cudaFuncSetAttribute(gemm_kernel,
                         cudaFuncAttributeMaxDynamicSharedMemorySize, SMEM_BYTES);

    detect_kernel<<<1, 256>>>((const int*)sources);
    split_w_kernel<<<(256 * FF + 255) / 256, 256>>>(W);

    clear_count_kernel<<<(NUM_NODES + 255) / 256, 256>>>();
    count_kernel<<<(NUM_EDGES + 255) / 256, 256>>>(targets);
    scan_kernel<<<1, 1024>>>();
    place_kernel<<<(NUM_EDGES + 255) / 256, 256>>>(sources, targets);
    gather_kernel<<<(NUM_NODES * 32 + 255) / 256, 256>>>(node_x);

    gemm_kernel<<<(NUM_NODES + 127) / 128, 256, SMEM_BYTES>>>(node_x, b, out);
}

// round 8
// speedup vs baseline: 1.5344x; 1.5344x over previous
#include <cuda_runtime.h>
#include <stdint.h>

#define NUM_NODES 50000
#define NUM_EDGES 600000
#define DD 128
#define FF 128
#define NB ((NUM_NODES + 255) / 256)   // 196 scan blocks

#define BK 16
#define A_STR 20    // 16 k + 4 pad -> conflict-free frag loads
#define B_STR 136   // 128 n + 8 pad -> conflict-free frag loads

// smem layout (uint32 units) inside one dynamic block
#define AH_OFF 0
#define AL_OFF (AH_OFF + 2 * 128 * A_STR)
#define BH_OFF (AL_OFF + 2 * 128 * A_STR)
#define BL_OFF (BH_OFF + 2 * BK * B_STR)
#define SMEM_WORDS (BL_OFF + 2 * BK * B_STR)
#define SMEM_BYTES (SMEM_WORDS * 4)   // 75776

// Scratch
__device__ float g_agg[NUM_NODES * DD];
__device__ int g_is64;
__device__ int g_start[NUM_NODES];   // CSR row starts
__device__ int g_cur[NUM_NODES];     // counts -> cursors -> row ends
__device__ int g_src[NUM_EDGES];     // source id per CSR slot
__device__ int g_bsum[NB];           // per-block sums for scan
__device__ uint32_t g_Wh[256 * FF], g_Wl[256 * FF];  // pre-split W

// ---------------------------------------------------------------------------
// Detect index dtype (int64 vs int32) from data pattern. Deterministic.
// ---------------------------------------------------------------------------
__global__ void detect_kernel(const int* __restrict__ w) {
    __shared__ int cnt;
    if (threadIdx.x == 0) cnt = 0;
    __syncthreads();
    int nz = 0;
    for (int i = threadIdx.x * 2 + 1; i < 2048; i += 2 * blockDim.x)
        nz += (w[i] != 0);
    atomicAdd(&cnt, nz);
    __syncthreads();
    if (threadIdx.x == 0) g_is64 = (cnt < 512) ? 1 : 0;
}

// ---------------------------------------------------------------------------
// Pre-split W into tf32 hi/lo
// ---------------------------------------------------------------------------
__device__ __forceinline__ void cvt_split(float f, uint32_t& h, uint32_t& l) {
    asm("cvt.rna.tf32.f32 %0, %1;" : "=r"(h) : "f"(f));
    float r = f - __uint_as_float(h);
    asm("cvt.rna.tf32.f32 %0, %1;" : "=r"(l) : "f"(r));
}

__global__ void split_w_kernel(const float* __restrict__ W) {
    int i = blockIdx.x * blockDim.x + threadIdx.x;
    if (i < 256 * FF) {
        uint32_t h, l;
        cvt_split(W[i], h, l);
        g_Wh[i] = h; g_Wl[i] = l;
    }
}

// ---------------------------------------------------------------------------
// CSR build
// ---------------------------------------------------------------------------
__global__ void clear_count_kernel() {
    int i = blockIdx.x * blockDim.x + threadIdx.x;
    if (i < NUM_NODES) g_cur[i] = 0;
}

__global__ void count_kernel(const void* __restrict__ tgt) {
    int e = blockIdx.x * blockDim.x + threadIdx.x;
    if (e >= NUM_EDGES) return;
    int t = g_is64 ? (int)reinterpret_cast<const long long*>(tgt)[e]
                   : reinterpret_cast<const int*>(tgt)[e];
    atomicAdd(&g_cur[t], 1);
}

// --- 3-pass multi-block exclusive scan over g_cur[NUM_NODES] ---
__global__ void scan1_kernel() {          // per-block reduce -> g_bsum
    __shared__ int sh[256];
    int i = blockIdx.x * 256 + threadIdx.x;
    sh[threadIdx.x] = (i < NUM_NODES) ? g_cur[i] : 0;
    __syncthreads();
    #pragma unroll
    for (int off = 128; off > 0; off >>= 1) {
        if (threadIdx.x < off) sh[threadIdx.x] += sh[threadIdx.x + off];
        __syncthreads();
    }
    if (threadIdx.x == 0) g_bsum[blockIdx.x] = sh[0];
}

__global__ void scan2_kernel() {          // exclusive scan of 196 block sums
    __shared__ int sh[256];
    int t = threadIdx.x;
    int v = (t < NB) ? g_bsum[t] : 0;
    sh[t] = v;
    __syncthreads();
    #pragma unroll
    for (int off = 1; off < 256; off <<= 1) {
        int u = (t >= off) ? sh[t - off] : 0;
        __syncthreads();
        sh[t] += u;
        __syncthreads();
    }
    if (t < NB) g_bsum[t] = sh[t] - v;    // exclusive prefix
}

__global__ void scan3_kernel() {          // per-block scan + offset -> start/cur
    __shared__ int sh[256];
    int i = blockIdx.x * 256 + threadIdx.x;
    int v = (i < NUM_NODES) ? g_cur[i] : 0;
    sh[threadIdx.x] = v;
    __syncthreads();
    #pragma unroll
    for (int off = 1; off < 256; off <<= 1) {
        int u = (threadIdx.x >= off) ? sh[threadIdx.x - off] : 0;
        __syncthreads();
        sh[threadIdx.x] += u;
        __syncthreads();
    }
    if (i < NUM_NODES) {
        int ex = sh[threadIdx.x] - v + g_bsum[blockIdx.x];
        g_start[i] = ex;
        g_cur[i] = ex;
    }
}

__global__ void place_kernel(const void* __restrict__ src,
                             const void* __restrict__ tgt) {
    int e = blockIdx.x * blockDim.x + threadIdx.x;
    if (e >= NUM_EDGES) return;
    int s, t;
    if (g_is64) {
        s = (int)reinterpret_cast<const long long*>(src)[e];
        t = (int)reinterpret_cast<const long long*>(tgt)[e];
    } else {
        s = reinterpret_cast<const int*>(src)[e];
        t = reinterpret_cast<const int*>(tgt)[e];
    }
    int pos = atomicAdd(&g_cur[t], 1);
    g_src[pos] = s;
}

// ---------------------------------------------------------------------------
// Gather: one warp per node, register accumulation, single write per row.
// After place_kernel, g_cur[n] == row end.
// ---------------------------------------------------------------------------
__global__ void gather_kernel(const float* __restrict__ x) {
    int n = (blockIdx.x * blockDim.x + threadIdx.x) >> 5;
    if (n >= NUM_NODES) return;
    int lane = threadIdx.x & 31;

    int beg = g_start[n], end = g_cur[n];
    float4 acc = make_float4(0.f, 0.f, 0.f, 0.f);

    int j = beg;
    for (; j + 4 <= end; j += 4) {
        int s0 = g_src[j], s1 = g_src[j + 1], s2 = g_src[j + 2], s3 = g_src[j + 3];
        float4 v0 = reinterpret_cast<const float4*>(x + (long long)s0 * DD)[lane];
        float4 v1 = reinterpret_cast<const float4*>(x + (long long)s1 * DD)[lane];
        float4 v2 = reinterpret_cast<const float4*>(x + (long long)s2 * DD)[lane];
        float4 v3 = reinterpret_cast<const float4*>(x + (long long)s3 * DD)[lane];
        acc.x += v0.x + v1.x + v2.x + v3.x;
        acc.y += v0.y + v1.y + v2.y + v3.y;
        acc.z += v0.z + v1.z + v2.z + v3.z;
        acc.w += v0.w + v1.w + v2.w + v3.w;
    }
    for (; j < end; j++) {
        int s = g_src[j];
        float4 v = reinterpret_cast<const float4*>(x + (long long)s * DD)[lane];
        acc.x += v.x; acc.y += v.y; acc.z += v.z; acc.w += v.w;
    }
    reinterpret_cast<float4*>(g_agg + (long long)n * DD)[lane] = acc;
}

// ---------------------------------------------------------------------------
// Tensor-core GEMM via 3xTF32: out = [agg|x] @ W + b,  M=50000, N=128, K=256.
// ---------------------------------------------------------------------------
__device__ __forceinline__ void mma_tf32(float* d, const uint32_t* a,
                                         uint32_t b0, uint32_t b1) {
    asm volatile(
        "mma.sync.aligned.m16n8k8.row.col.f32.tf32.tf32.f32 "
        "{%0,%1,%2,%3}, {%4,%5,%6,%7}, {%8,%9}, {%0,%1,%2,%3};"
        : "+f"(d[0]), "+f"(d[1]), "+f"(d[2]), "+f"(d[3])
        : "r"(a[0]), "r"(a[1]), "r"(a[2]), "r"(a[3]), "r"(b0), "r"(b1));
}

__device__ __forceinline__ void load_chunk(
    const float* __restrict__ hbase, int k0,
    uint32_t* __restrict__ Ah, uint32_t* __restrict__ Al,
    uint32_t* __restrict__ Bh, uint32_t* __restrict__ Bl,
    int tid, int nbase)
{
    #pragma unroll
    for (int i = 0; i < 2; i++) {
        int idx = tid + i * 256;
        int r = idx >> 2, q = idx & 3;
        int node = nbase + r;
        float4 v = make_float4(0.f, 0.f, 0.f, 0.f);
        if (node < NUM_NODES)
            v = *reinterpret_cast<const float4*>(hbase + (long long)node * DD + q * 4);
        uint32_t h0,l0,h1,l1,h2,l2,h3,l3;
        cvt_split(v.x, h0, l0); cvt_split(v.y, h1, l1);
        cvt_split(v.z, h2, l2); cvt_split(v.w, h3, l3);
        int o = r * A_STR + q * 4;
        Ah[o] = h0; Ah[o+1] = h1; Ah[o+2] = h2; Ah[o+3] = h3;
        Al[o] = l0; Al[o+1] = l1; Al[o+2] = l2; Al[o+3] = l3;
    }
    #pragma unroll
    for (int i = 0; i < 2; i++) {
        int idx = tid + i * 256;
        int r = idx >> 5, q = idx & 31;
        uint4 vh = *reinterpret_cast<const uint4*>(g_Wh + (k0 + r) * FF + q * 4);
        uint4 vl = *reinterpret_cast<const uint4*>(g_Wl + (k0 + r) * FF + q * 4);
        int o = r * B_STR + q * 4;
        *reinterpret_cast<uint4*>(Bh + o) = vh;
        *reinterpret_cast<uint4*>(Bl + o) = vl;
    }
}

__global__ void __launch_bounds__(256, 2)
gemm_kernel(const float* __restrict__ x,
            const float* __restrict__ b, float* __restrict__ out) {
    extern __shared__ uint32_t smem[];
    uint32_t* AhB = smem + AH_OFF;
    uint32_t* AlB = smem + AL_OFF;
    uint32_t* BhB = smem + BH_OFF;
    uint32_t* BlB = smem + BL_OFF;

    int tid = threadIdx.x;
    int lane = tid & 31, wid = tid >> 5;
    int gid = lane >> 2, tig = lane & 3;
    int wm = wid & 3;
    int wn = wid >> 2;
    int nbase = blockIdx.x * 128;

    float acc[2][8][4];
    #pragma unroll
    for (int mt = 0; mt < 2; mt++)
        #pragma unroll
        for (int nt = 0; nt < 8; nt++)
            #pragma unroll
            for (int f = 0; f < 4; f++) acc[mt][nt][f] = 0.f;

    load_chunk(g_agg, 0, AhB, AlB, BhB, BlB, tid, nbase);
    __syncthreads();

    for (int c = 0; c < 16; c++) {
        if (c + 1 < 16) {
            int k0 = (c + 1) * BK;
            const float* hbase = (k0 < 128) ? (g_agg + k0) : (x + k0 - 128);
            int nb = (c + 1) & 1;
            load_chunk(hbase, k0,
                       AhB + nb * 128 * A_STR, AlB + nb * 128 * A_STR,
                       BhB + nb * BK * B_STR,  BlB + nb * BK * B_STR,
                       tid, nbase);
        }
        int cb = c & 1;
        const uint32_t* cAh = AhB + cb * 128 * A_STR;
        const uint32_t* cAl = AlB + cb * 128 * A_STR;
        const uint32_t* cBh = BhB + cb * BK * B_STR;
        const uint32_t* cBl = BlB + cb * BK * B_STR;

        #pragma unroll
        for (int ks = 0; ks < 2; ks++) {
            uint32_t ah[2][4], al[2][4];
            #pragma unroll
            for (int mt = 0; mt < 2; mt++) {
                int m = wm * 32 + mt * 16 + gid;
                int ro = m * A_STR + ks * 8 + tig;
                ah[mt][0] = cAh[ro];
                ah[mt][1] = cAh[ro + 8 * A_STR];
                ah[mt][2] = cAh[ro + 4];
                ah[mt][3] = cAh[ro + 8 * A_STR + 4];
                al[mt][0] = cAl[ro];
                al[mt][1] = cAl[ro + 8 * A_STR];
                al[mt][2] = cAl[ro + 4];
                al[mt][3] = cAl[ro + 8 * A_STR + 4];
            }
            #pragma unroll
            for (int nt = 0; nt < 8; nt++) {
                int n = wn * 64 + nt * 8 + gid;
                int bo = (ks * 8 + tig) * B_STR + n;
                uint32_t b0h = cBh[bo], b1h = cBh[bo + 4 * B_STR];
                uint32_t b0l = cBl[bo], b1l = cBl[bo + 4 * B_STR];
                #pragma unroll
                for (int mt = 0; mt < 2; mt++) {
                    mma_tf32(acc[mt][nt], ah[mt], b0h, b1h);
                    mma_tf32(acc[mt][nt], ah[mt], b0l, b1l);
                    mma_tf32(acc[mt][nt], al[mt], b0h, b1h);
                }
            }
        }
        __syncthreads();
    }

    #pragma unroll
    for (int mt = 0; mt < 2; mt++) {
        #pragma unroll
        for (int nt = 0; nt < 8; nt++) {
            int col = wn * 64 + nt * 8 + tig * 2;
            float2 bb = *reinterpret_cast<const float2*>(b + col);
            int row0 = nbase + wm * 32 + mt * 16 + gid;
            if (row0 < NUM_NODES) {
                float2 o = make_float2(acc[mt][nt][0] + bb.x, acc[mt][nt][1] + bb.y);
                *reinterpret_cast<float2*>(out + (long long)row0 * FF + col) = o;
            }
            int row1 = row0 + 8;
            if (row1 < NUM_NODES) {
                float2 o = make_float2(acc[mt][nt][2] + bb.x, acc[mt][nt][3] + bb.y);
                *reinterpret_cast<float2*>(out + (long long)row1 * FF + col) = o;
            }
        }
    }
}

extern "C" void kernel_launch(void* const* d_in, const int* in_sizes, int n_in,
                              void* d_out, int out_size) {
    const float* node_x = (const float*)d_in[0];
    const void*  sources = d_in[1];
    const void*  targets = d_in[2];
    const float* W = (const float*)d_in[3];
    const float* b = (const float*)d_in[4];
    float* out = (float*)d_out;

    cudaFuncSetAttribute(gemm_kernel,
                         cudaFuncAttributeMaxDynamicSharedMemorySize, SMEM_BYTES);

    detect_kernel<<<1, 256>>>((const int*)sources);
    split_w_kernel<<<(256 * FF + 255) / 256, 256>>>(W);

    clear_count_kernel<<<NB, 256>>>();
    count_kernel<<<(NUM_EDGES + 255) / 256, 256>>>(targets);
    scan1_kernel<<<NB, 256>>>();
    scan2_kernel<<<1, 256>>>();
    scan3_kernel<<<NB, 256>>>();
    place_kernel<<<(NUM_EDGES + 255) / 256, 256>>>(sources, targets);
    gather_kernel<<<(NUM_NODES * 32 + 255) / 256, 256>>>(node_x);

    gemm_kernel<<<(NUM_NODES + 127) / 128, 256, SMEM_BYTES>>>(node_x, b, out);
}

// round 9
// speedup vs baseline: 1.8413x; 1.2000x over previous
#include <cuda_runtime.h>
#include <stdint.h>

#define NUM_NODES 50000
#define NUM_EDGES 600000
#define DD 128
#define FF 128
#define NB ((NUM_NODES + 255) / 256)   // 196 scan blocks

#define BK 16
#define A_STR 12   // 8 bf16x2 pairs + 4 pad words -> conflict-free frag loads
#define B_STR 12

// smem layout (uint32 words): 4 regions x 2 buffers x 1536 words = 48 KB
#define REG_WORDS (128 * A_STR)        // 1536
#define AH_OFF 0
#define AL_OFF (AH_OFF + 2 * REG_WORDS)
#define BH_OFF (AL_OFF + 2 * REG_WORDS)
#define BL_OFF (BH_OFF + 2 * REG_WORDS)
#define SMEM_WORDS (BL_OFF + 2 * REG_WORDS)
#define SMEM_BYTES (SMEM_WORDS * 4)    // 49152

// Scratch
__device__ float g_agg[NUM_NODES * DD];
__device__ int g_is64;
__device__ int g_start[NUM_NODES];
__device__ int g_cur[NUM_NODES];
__device__ int g_src[NUM_EDGES];
__device__ int g_bsum[NB];
// W pre-packed: transposed, k-pairs packed bf16x2, hi/lo. [n][kpair], 128x128
__device__ uint32_t g_Wbh[128 * 128], g_Wbl[128 * 128];

// ---------------------------------------------------------------------------
// bf16 pack helpers: reg = {hi half: f_hi (k+1), lo half: f_lo (k)}
// ---------------------------------------------------------------------------
__device__ __forceinline__ uint32_t pack_bf16(float f_lo, float f_hi) {
    uint32_t r;
    asm("cvt.rn.bf16x2.f32 %0, %1, %2;" : "=r"(r) : "f"(f_hi), "f"(f_lo));
    return r;
}
// residuals of a packed hi reg vs the original floats
__device__ __forceinline__ void resid_bf16(uint32_t hi, float f_lo, float f_hi,
                                           float& r_lo, float& r_hi) {
    r_lo = f_lo - __uint_as_float(hi << 16);
    r_hi = f_hi - __uint_as_float(hi & 0xFFFF0000u);
}

// ---------------------------------------------------------------------------
// Detect index dtype (int64 vs int32) from data pattern. Deterministic.
// ---------------------------------------------------------------------------
__global__ void detect_kernel(const int* __restrict__ w) {
    __shared__ int cnt;
    if (threadIdx.x == 0) cnt = 0;
    __syncthreads();
    int nz = 0;
    for (int i = threadIdx.x * 2 + 1; i < 2048; i += 2 * blockDim.x)
        nz += (w[i] != 0);
    atomicAdd(&cnt, nz);
    __syncthreads();
    if (threadIdx.x == 0) g_is64 = (cnt < 512) ? 1 : 0;
}

// ---------------------------------------------------------------------------
// Pre-pack W: g_Wb*[n][p] = bf16x2(W[2p][n], W[2p+1][n]), hi + lo split
// ---------------------------------------------------------------------------
__global__ void split_w_kernel(const float* __restrict__ W) {
    int i = blockIdx.x * blockDim.x + threadIdx.x;
    if (i >= 128 * 128) return;
    int n = i >> 7, p = i & 127;
    float f0 = W[(2 * p) * FF + n];
    float f1 = W[(2 * p + 1) * FF + n];
    uint32_t hi = pack_bf16(f0, f1);
    float r0, r1;
    resid_bf16(hi, f0, f1, r0, r1);
    g_Wbh[n * 128 + p] = hi;
    g_Wbl[n * 128 + p] = pack_bf16(r0, r1);
}

// ---------------------------------------------------------------------------
// CSR build
// ---------------------------------------------------------------------------
__global__ void clear_count_kernel() {
    int i = blockIdx.x * blockDim.x + threadIdx.x;
    if (i < NUM_NODES) g_cur[i] = 0;
}

__global__ void count_kernel(const void* __restrict__ tgt) {
    int e = blockIdx.x * blockDim.x + threadIdx.x;
    if (e >= NUM_EDGES) return;
    int t = g_is64 ? (int)reinterpret_cast<const long long*>(tgt)[e]
                   : reinterpret_cast<const int*>(tgt)[e];
    atomicAdd(&g_cur[t], 1);
}

__global__ void scan1_kernel() {
    __shared__ int sh[256];
    int i = blockIdx.x * 256 + threadIdx.x;
    sh[threadIdx.x] = (i < NUM_NODES) ? g_cur[i] : 0;
    __syncthreads();
    #pragma unroll
    for (int off = 128; off > 0; off >>= 1) {
        if (threadIdx.x < off) sh[threadIdx.x] += sh[threadIdx.x + off];
        __syncthreads();
    }
    if (threadIdx.x == 0) g_bsum[blockIdx.x] = sh[0];
}

__global__ void scan2_kernel() {
    __shared__ int sh[256];
    int t = threadIdx.x;
    int v = (t < NB) ? g_bsum[t] : 0;
    sh[t] = v;
    __syncthreads();
    #pragma unroll
    for (int off = 1; off < 256; off <<= 1) {
        int u = (t >= off) ? sh[t - off] : 0;
        __syncthreads();
        sh[t] += u;
        __syncthreads();
    }
    if (t < NB) g_bsum[t] = sh[t] - v;
}

__global__ void scan3_kernel() {
    __shared__ int sh[256];
    int i = blockIdx.x * 256 + threadIdx.x;
    int v = (i < NUM_NODES) ? g_cur[i] : 0;
    sh[threadIdx.x] = v;
    __syncthreads();
    #pragma unroll
    for (int off = 1; off < 256; off <<= 1) {
        int u = (threadIdx.x >= off) ? sh[threadIdx.x - off] : 0;
        __syncthreads();
        sh[threadIdx.x] += u;
        __syncthreads();
    }
    if (i < NUM_NODES) {
        int ex = sh[threadIdx.x] - v + g_bsum[blockIdx.x];
        g_start[i] = ex;
        g_cur[i] = ex;
    }
}

__global__ void place_kernel(const void* __restrict__ src,
                             const void* __restrict__ tgt) {
    int e = blockIdx.x * blockDim.x + threadIdx.x;
    if (e >= NUM_EDGES) return;
    int s, t;
    if (g_is64) {
        s = (int)reinterpret_cast<const long long*>(src)[e];
        t = (int)reinterpret_cast<const long long*>(tgt)[e];
    } else {
        s = reinterpret_cast<const int*>(src)[e];
        t = reinterpret_cast<const int*>(tgt)[e];
    }
    int pos = atomicAdd(&g_cur[t], 1);
    g_src[pos] = s;
}

// ---------------------------------------------------------------------------
// Gather: one warp per node, register accumulation, single write per row.
// ---------------------------------------------------------------------------
__global__ void gather_kernel(const float* __restrict__ x) {
    int n = (blockIdx.x * blockDim.x + threadIdx.x) >> 5;
    if (n >= NUM_NODES) return;
    int lane = threadIdx.x & 31;

    int beg = g_start[n], end = g_cur[n];
    float4 acc = make_float4(0.f, 0.f, 0.f, 0.f);

    int j = beg;
    for (; j + 4 <= end; j += 4) {
        int s0 = g_src[j], s1 = g_src[j + 1], s2 = g_src[j + 2], s3 = g_src[j + 3];
        float4 v0 = reinterpret_cast<const float4*>(x + (long long)s0 * DD)[lane];
        float4 v1 = reinterpret_cast<const float4*>(x + (long long)s1 * DD)[lane];
        float4 v2 = reinterpret_cast<const float4*>(x + (long long)s2 * DD)[lane];
        float4 v3 = reinterpret_cast<const float4*>(x + (long long)s3 * DD)[lane];
        acc.x += v0.x + v1.x + v2.x + v3.x;
        acc.y += v0.y + v1.y + v2.y + v3.y;
        acc.z += v0.z + v1.z + v2.z + v3.z;
        acc.w += v0.w + v1.w + v2.w + v3.w;
    }
    for (; j < end; j++) {
        int s = g_src[j];
        float4 v = reinterpret_cast<const float4*>(x + (long long)s * DD)[lane];
        acc.x += v.x; acc.y += v.y; acc.z += v.z; acc.w += v.w;
    }
    reinterpret_cast<float4*>(g_agg + (long long)n * DD)[lane] = acc;
}

// ---------------------------------------------------------------------------
// Tensor-core GEMM via bf16x3: out = [agg|x] @ W + b.
// mma.m16n8k16 bf16: a*b ~= ah*bh + ah*bl + al*bh  (error ~3e-5)
// CTA 128x128, 8 warps (4m x 2n), BK=16 (one mma K-depth per chunk).
// ---------------------------------------------------------------------------
__device__ __forceinline__ void mma_bf16(float* d, const uint32_t* a,
                                         uint32_t b0, uint32_t b1) {
    asm volatile(
        "mma.sync.aligned.m16n8k16.row.col.f32.bf16.bf16.f32 "
        "{%0,%1,%2,%3}, {%4,%5,%6,%7}, {%8,%9}, {%0,%1,%2,%3};"
        : "+f"(d[0]), "+f"(d[1]), "+f"(d[2]), "+f"(d[3])
        : "r"(a[0]), "r"(a[1]), "r"(a[2]), "r"(a[3]), "r"(b0), "r"(b1));
}

// Load one K=16 chunk: A from fp32 source (split on the fly), B pure copies.
__device__ __forceinline__ void load_chunk(
    const float* __restrict__ hbase, int c,
    uint32_t* __restrict__ Ah, uint32_t* __restrict__ Al,
    uint32_t* __restrict__ Bh, uint32_t* __restrict__ Bl,
    int tid, int nbase)
{
    // A: 128 rows x 8 pairs; thread -> half-row (r = tid>>1, pairs 4h..4h+3)
    {
        int r = tid >> 1, h = tid & 1;
        int node = nbase + r;
        float4 v0 = make_float4(0.f, 0.f, 0.f, 0.f), v1 = v0;
        if (node < NUM_NODES) {
            const float4* p = reinterpret_cast<const float4*>(
                hbase + (long long)node * DD) + h * 2;
            v0 = p[0]; v1 = p[1];
        }
        uint32_t h0 = pack_bf16(v0.x, v0.y);
        uint32_t h1 = pack_bf16(v0.z, v0.w);
        uint32_t h2 = pack_bf16(v1.x, v1.y);
        uint32_t h3 = pack_bf16(v1.z, v1.w);
        float ra, rb;
        uint32_t l0, l1, l2, l3;
        resid_bf16(h0, v0.x, v0.y, ra, rb); l0 = pack_bf16(ra, rb);
        resid_bf16(h1, v0.z, v0.w, ra, rb); l1 = pack_bf16(ra, rb);
        resid_bf16(h2, v1.x, v1.y, ra, rb); l2 = pack_bf16(ra, rb);
        resid_bf16(h3, v1.z, v1.w, ra, rb); l3 = pack_bf16(ra, rb);
        int o = r * A_STR + h * 4;
        *reinterpret_cast<uint4*>(Ah + o) = make_uint4(h0, h1, h2, h3);
        *reinterpret_cast<uint4*>(Al + o) = make_uint4(l0, l1, l2, l3);
    }
    // B: copy pre-packed W pairs for this chunk (pairs c*8 .. c*8+7)
    {
        int n = tid >> 1, h = tid & 1;
        int go = n * 128 + c * 8 + h * 4;
        int o = n * B_STR + h * 4;
        *reinterpret_cast<uint4*>(Bh + o) =
            *reinterpret_cast<const uint4*>(g_Wbh + go);
        *reinterpret_cast<uint4*>(Bl + o) =
            *reinterpret_cast<const uint4*>(g_Wbl + go);
    }
}

__global__ void __launch_bounds__(256, 2)
gemm_kernel(const float* __restrict__ x,
            const float* __restrict__ b, float* __restrict__ out) {
    extern __shared__ uint32_t smem[];
    uint32_t* AhB = smem + AH_OFF;
    uint32_t* AlB = smem + AL_OFF;
    uint32_t* BhB = smem + BH_OFF;
    uint32_t* BlB = smem + BL_OFF;

    int tid = threadIdx.x;
    int lane = tid & 31, wid = tid >> 5;
    int gid = lane >> 2, tig = lane & 3;
    int wm = wid & 3;          // 32-row slab
    int wn = wid >> 2;         // 64-col slab
    int nbase = blockIdx.x * 128;

    float acc[2][8][4];
    #pragma unroll
    for (int mt = 0; mt < 2; mt++)
        #pragma unroll
        for (int nt = 0; nt < 8; nt++)
            #pragma unroll
            for (int f = 0; f < 4; f++) acc[mt][nt][f] = 0.f;

    load_chunk(g_agg, 0, AhB, AlB, BhB, BlB, tid, nbase);
    __syncthreads();

    for (int c = 0; c < 16; c++) {
        if (c + 1 < 16) {
            int k0 = (c + 1) * BK;
            const float* hbase = (k0 < 128) ? (g_agg + k0) : (x + k0 - 128);
            int nb = (c + 1) & 1;
            load_chunk(hbase, c + 1,
                       AhB + nb * REG_WORDS, AlB + nb * REG_WORDS,
                       BhB + nb * REG_WORDS, BlB + nb * REG_WORDS,
                       tid, nbase);
        }
        int cb = c & 1;
        const uint32_t* cAh = AhB + cb * REG_WORDS;
        const uint32_t* cAl = AlB + cb * REG_WORDS;
        const uint32_t* cBh = BhB + cb * REG_WORDS;
        const uint32_t* cBl = BlB + cb * REG_WORDS;

        // A fragments: rows (gid, gid+8), k-pairs (tig, tig+4)
        uint32_t ah[2][4], al[2][4];
        #pragma unroll
        for (int mt = 0; mt < 2; mt++) {
            int m = wm * 32 + mt * 16 + gid;
            int o = m * A_STR + tig;
            ah[mt][0] = cAh[o];
            ah[mt][1] = cAh[o + 8 * A_STR];
            ah[mt][2] = cAh[o + 4];
            ah[mt][3] = cAh[o + 8 * A_STR + 4];
            al[mt][0] = cAl[o];
            al[mt][1] = cAl[o + 8 * A_STR];
            al[mt][2] = cAl[o + 4];
            al[mt][3] = cAl[o + 8 * A_STR + 4];
        }
        #pragma unroll
        for (int nt = 0; nt < 8; nt++) {
            int n = wn * 64 + nt * 8 + gid;
            int bo = n * B_STR + tig;
            uint32_t b0h = cBh[bo], b1h = cBh[bo + 4];
            uint32_t b0l = cBl[bo], b1l = cBl[bo + 4];
            #pragma unroll
            for (int mt = 0; mt < 2; mt++) {
                mma_bf16(acc[mt][nt], ah[mt], b0h, b1h);   // hi*hi
                mma_bf16(acc[mt][nt], ah[mt], b0l, b1l);   // hi*lo
                mma_bf16(acc[mt][nt], al[mt], b0h, b1h);   // lo*hi
            }
        }
        __syncthreads();
    }

    #pragma unroll
    for (int mt = 0; mt < 2; mt++) {
        #pragma unroll
        for (int nt = 0; nt < 8; nt++) {
            int col = wn * 64 + nt * 8 + tig * 2;
            float2 bb = *reinterpret_cast<const float2*>(b + col);
            int row0 = nbase + wm * 32 + mt * 16 + gid;
            if (row0 < NUM_NODES) {
                float2 o = make_float2(acc[mt][nt][0] + bb.x, acc[mt][nt][1] + bb.y);
                *reinterpret_cast<float2*>(out + (long long)row0 * FF + col) = o;
            }
            int row1 = row0 + 8;
            if (row1 < NUM_NODES) {
                float2 o = make_float2(acc[mt][nt][2] + bb.x, acc[mt][nt][3] + bb.y);
                *reinterpret_cast<float2*>(out + (long long)row1 * FF + col) = o;
            }
        }
    }
}

extern "C" void kernel_launch(void* const* d_in, const int* in_sizes, int n_in,
                              void* d_out, int out_size) {
    const float* node_x = (const float*)d_in[0];
    const void*  sources = d_in[1];
    const void*  targets = d_in[2];
    const float* W = (const float*)d_in[3];
    const float* b = (const float*)d_in[4];
    float* out = (float*)d_out;

    cudaFuncSetAttribute(gemm_kernel,
                         cudaFuncAttributeMaxDynamicSharedMemorySize, SMEM_BYTES);

    detect_kernel<<<1, 256>>>((const int*)sources);
    split_w_kernel<<<(128 * 128 + 255) / 256, 256>>>(W);

    clear_count_kernel<<<NB, 256>>>();
    count_kernel<<<(NUM_EDGES + 255) / 256, 256>>>(targets);
    scan1_kernel<<<NB, 256>>>();
    scan2_kernel<<<1, 256>>>();
    scan3_kernel<<<NB, 256>>>();
    place_kernel<<<(NUM_EDGES + 255) / 256, 256>>>(sources, targets);
    gather_kernel<<<(NUM_NODES * 32 + 255) / 256, 256>>>(node_x);

    gemm_kernel<<<(NUM_NODES + 127) / 128, 256, SMEM_BYTES>>>(node_x, b, out);
}